// round 7
// baseline (speedup 1.0000x reference)
#include <cuda_runtime.h>
#include <cuda_bf16.h>
#include <math.h>

// ---------------------------------------------------------------------------
// PhysicsAwareMSELoss — ONE fused kernel.
//   sample blocks (B): 256 threads x 8 elems; block reduces 7 sums; thread 0
//                      finishes per-sample math -> g_samp[4][b].
//   strip blocks (64): each warp screens 32 fixed pairs from smem scalars,
//                      ballot-walks survivors in lane order, warp-reduces D
//                      only for needed pairs -> g_pairAcc[4][strip].
//   epilogue: ONLY thread 0 per block: __threadfence + ticket atomic
//             (192 fences total, not 80K). Last block acquires, sums the
//             768 partial floats, writes out[0], resets ticket.
// ---------------------------------------------------------------------------

#define MAXB    256
#define MAXSTRP 256
#define ALPHA   0.7f
#define BETA    0.3f
#define STRIP   256     // pairs per strip block (8 warps x 32)

__device__ float g_samp[4][MAXB];        // 0:wmse 1:el_err 2:el_valid 3:mono
__device__ float g_pairAcc[4][MAXSTRP];  // 0:tsum 1:tcnt 2:ssum 3:scnt
__device__ unsigned int g_ticket;        // zero-init; reset by last block

__device__ __forceinline__ float reluf(float x) { return fmaxf(x, 0.f); }

__device__ __forceinline__ void pair_masks(int mi, int mj,
                                           float sri, float srj,
                                           float ti, float tj,
                                           bool& tmask_ij, bool& smask_ij)
{
    bool same   = (mi == mj);
    float hi    = fmaxf(sri, srj);
    float lo    = fminf(sri, srj);
    float ratio = hi / (lo + 1e-8f);
    float tdiff = ti - tj;
    tmask_ij = same && (ratio <= 1.2f) && (fabsf(tdiff) >= 10.f) && (tdiff > 0.f);
    smask_ij = same && (fabsf(tdiff) <= 10.f) && (ratio >= 1.2f) && (sri > srj);
}

__global__ void __launch_bounds__(256)
fused_kernel(const float* __restrict__ pred,
             const float* __restrict__ target,
             const int*   __restrict__ mat,
             const float* __restrict__ strain,
             const float* __restrict__ E,
             const float* __restrict__ temp,
             const float* __restrict__ sr,
             const float* __restrict__ w,
             float* __restrict__ out,
             int B, int S, int nStrips)
{
    const int tid  = threadIdx.x;
    const int lane = tid & 31;
    const int wid  = tid >> 5;

    __shared__ float sh[7][8];
    __shared__ bool  sh_last;

    if (blockIdx.x < (unsigned)B) {
        // ---------------- one block per sample: stats + per-sample math ----------
        const int b = blockIdx.x;
        const float* p = pred   + (size_t)b * S;
        const float* t = target + (size_t)b * S;
        const float* e = strain + (size_t)b * S;

        float v[7];   // d2, cnt, sx, sy, sxy, sxx, mono
        #pragma unroll
        for (int k = 0; k < 7; k++) v[k] = 0.f;

        for (int base = 0; base < S; base += 2048) {
            const int e0 = base + tid * 8;
            if (e0 + 7 < S) {
                float4 p0 = *reinterpret_cast<const float4*>(p + e0);
                float4 p1 = *reinterpret_cast<const float4*>(p + e0 + 4);
                float4 t0 = *reinterpret_cast<const float4*>(t + e0);
                float4 t1 = *reinterpret_cast<const float4*>(t + e0 + 4);
                float4 ea = *reinterpret_cast<const float4*>(e + e0);
                float4 eb = *reinterpret_cast<const float4*>(e + e0 + 4);

                float pv[8] = {p0.x,p0.y,p0.z,p0.w,p1.x,p1.y,p1.z,p1.w};
                float tv[8] = {t0.x,t0.y,t0.z,t0.w,t1.x,t1.y,t1.z,t1.w};
                float ev[8] = {ea.x,ea.y,ea.z,ea.w,eb.x,eb.y,eb.z,eb.w};

                #pragma unroll
                for (int q = 0; q < 8; q++) {
                    float d = pv[q] - tv[q];
                    v[0] += d * d;
                    if (ev[q] < 0.02f) {
                        v[1] += 1.f; v[2] += ev[q]; v[3] += pv[q];
                        v[4] += ev[q] * pv[q]; v[5] += ev[q] * ev[q];
                    }
                }
                #pragma unroll
                for (int q = 0; q < 7; q++)
                    v[6] += reluf(pv[q] - pv[q + 1]);
                float nxt = __shfl_down_sync(0xFFFFFFFFu, pv[0], 1);
                if (lane == 31) nxt = (e0 + 8 < S) ? p[e0 + 8] : pv[7]; // => relu 0
                v[6] += reluf(pv[7] - nxt);
            } else if (e0 < S) {
                for (int i = e0; i < S && i < e0 + 8; i++) {
                    float pvv = p[i], tvv = t[i], evv = e[i];
                    float d = pvv - tvv; v[0] += d * d;
                    if (evv < 0.02f) { v[1] += 1.f; v[2] += evv; v[3] += pvv;
                                       v[4] += evv*pvv; v[5] += evv*evv; }
                    if (i < S - 1) v[6] += reluf(pvv - p[i + 1]);
                }
            }
        }

        #pragma unroll
        for (int k = 0; k < 7; k++) {
            #pragma unroll
            for (int off = 16; off > 0; off >>= 1)
                v[k] += __shfl_xor_sync(0xFFFFFFFFu, v[k], off);
        }
        if (lane == 0) {
            #pragma unroll
            for (int k = 0; k < 7; k++) sh[k][wid] = v[k];
        }
        __syncthreads();
        if (tid == 0) {
            float r[7];
            #pragma unroll
            for (int k = 0; k < 7; k++) {
                r[k] = 0.f;
                #pragma unroll
                for (int q = 0; q < 8; q++) r[k] += sh[k][q];
            }
            float wmse = (r[0] / (float)S) * w[mat[b]];
            float cnt = r[1], Sx = r[2], Sy = r[3], Sxy = r[4], Sxx = r[5];
            float el_err = 0.f, el_valid = 0.f;
            if (cnt >= 2.f) {
                float safe  = fmaxf(cnt, 1.f);
                float eps_m = Sx / safe;
                float sig_m = Sy / safe;
                float cov = Sxy - sig_m * Sx - eps_m * Sy + cnt * eps_m * sig_m;
                float var = Sxx - 2.f * eps_m * Sx + cnt * eps_m * eps_m;
                float et  = E[b] * 1000.f;
                el_err   = fabsf(cov / (var + 1e-8f) - et) / (et + 1e-8f);
                el_valid = 1.f;
            }
            g_samp[0][b] = wmse;
            g_samp[1][b] = el_err;
            g_samp[2][b] = el_valid;
            g_samp[3][b] = r[6];
        }
    } else {
        // ------------- strip of pairs: screen + sparse reduce + accumulate ------
        __shared__ int   s_mat[MAXB];
        __shared__ float s_sr[MAXB];
        __shared__ float s_temp[MAXB];

        const int strip = blockIdx.x - B;
        const int totalPairs = B * B;

        for (int b = tid; b < B; b += 256) {
            s_mat[b]  = mat[b];
            s_sr[b]   = sr[b];
            s_temp[b] = temp[b];
        }
        __syncthreads();

        const int idx = strip * STRIP + tid;
        bool t_ij = false, s_ji = false;
        int  myi = 0, myj = 0;
        if (idx < totalPairs) {
            myi = idx / B;
            myj = idx - myi * B;
            bool sd, td;
            pair_masks(s_mat[myi], s_mat[myj], s_sr[myi], s_sr[myj],
                       s_temp[myi], s_temp[myj], t_ij, sd);
            pair_masks(s_mat[myj], s_mat[myi], s_sr[myj], s_sr[myi],
                       s_temp[myj], s_temp[myi], td, s_ji);
        }
        const bool need = t_ij || s_ji;

        unsigned bal = __ballot_sync(0xFFFFFFFFu, need);
        float tsum = 0.f, tcnt = 0.f, ssum = 0.f, scnt = 0.f;
        const int S4 = S >> 2;
        while (bal) {
            const int src = __ffs(bal) - 1;
            bal &= bal - 1;
            const int i  = __shfl_sync(0xFFFFFFFFu, myi, src);
            const int j  = __shfl_sync(0xFFFFFFFFu, myj, src);
            const int tt = __shfl_sync(0xFFFFFFFFu, (int)t_ij, src);
            const int ss = __shfl_sync(0xFFFFFFFFu, (int)s_ji, src);

            const float4* si = reinterpret_cast<const float4*>(pred + (size_t)i * S);
            const float4* sj = reinterpret_cast<const float4*>(pred + (size_t)j * S);
            float acc = 0.f;
            #pragma unroll 4
            for (int k = lane; k < S4; k += 32) {
                float4 a = si[k], bq = sj[k];
                acc += reluf(a.x - bq.x) + reluf(a.y - bq.y)
                     + reluf(a.z - bq.z) + reluf(a.w - bq.w);
            }
            #pragma unroll
            for (int off = 16; off > 0; off >>= 1)
                acc += __shfl_xor_sync(0xFFFFFFFFu, acc, off);
            const float D = acc / (float)S;
            if (tt) { tsum += D; tcnt += 1.f; }
            if (ss) { ssum += D; scnt += 1.f; }
        }

        if (lane == 0) {
            sh[0][wid] = tsum; sh[1][wid] = tcnt;
            sh[2][wid] = ssum; sh[3][wid] = scnt;
        }
        __syncthreads();
        if (tid == 0) {
            float r0 = 0.f, r1 = 0.f, r2 = 0.f, r3 = 0.f;
            #pragma unroll
            for (int q = 0; q < 8; q++) {
                r0 += sh[0][q]; r1 += sh[1][q];
                r2 += sh[2][q]; r3 += sh[3][q];
            }
            g_pairAcc[0][strip] = r0;
            g_pairAcc[1][strip] = r1;
            g_pairAcc[2][strip] = r2;
            g_pairAcc[3][strip] = r3;
        }
    }

    // ================= epilogue: release by thread 0 only ====================
    if (tid == 0) {
        __threadfence();                           // release the 4 floats above
        unsigned int v = atomicAdd(&g_ticket, 1u); // 192 atomics total
        sh_last = (v == gridDim.x - 1);
    }
    __syncthreads();
    if (!sh_last) return;
    __threadfence();                               // acquire

    // ---- last block: sum 4*B + 4*nStrips floats, write scalar ----
    float acc8[8];
    #pragma unroll
    for (int k = 0; k < 8; k++) acc8[k] = 0.f;

    for (int b = tid; b < B; b += 256) {
        acc8[0] += g_samp[0][b];
        acc8[1] += g_samp[1][b];
        acc8[2] += g_samp[2][b];
        acc8[3] += g_samp[3][b];
    }
    for (int s = tid; s < nStrips; s += 256) {
        acc8[4] += g_pairAcc[0][s];
        acc8[5] += g_pairAcc[1][s];
        acc8[6] += g_pairAcc[2][s];
        acc8[7] += g_pairAcc[3][s];
    }

    #pragma unroll
    for (int k = 0; k < 8; k++) {
        #pragma unroll
        for (int off = 16; off > 0; off >>= 1)
            acc8[k] += __shfl_xor_sync(0xFFFFFFFFu, acc8[k], off);
    }
    __syncthreads();                 // reuse sh[][] safely
    if (lane == 0) {
        #pragma unroll
        for (int k = 0; k < 7; k++) sh[k][wid] = acc8[k];
    }
    __shared__ float sh7[8];
    if (lane == 0) sh7[wid] = acc8[7];
    __syncthreads();
    if (tid == 0) {
        float r[8];
        #pragma unroll
        for (int k = 0; k < 8; k++) r[k] = 0.f;
        #pragma unroll
        for (int q = 0; q < 8; q++) {
            #pragma unroll
            for (int k = 0; k < 7; k++) r[k] += sh[k][q];
            r[7] += sh7[q];
        }
        float mse_loss  = r[0] / (float)B;
        float elastic   = (r[2] > 0.f) ? r[1] / fmaxf(r[2], 1.f) : 0.f;
        float mono      = r[3] / (float)(B * (S - 1));
        float temp_loss = (r[5] > 0.f) ? r[4] / fmaxf(r[5], 1.f) : 0.f;
        float sr_loss   = (r[7] > 0.f) ? r[6] / fmaxf(r[7], 1.f) : 0.f;
        out[0] = ALPHA * mse_loss + BETA * (elastic + mono + temp_loss + sr_loss);
        g_ticket = 0;   // reset for next graph replay
    }
}

// --------------------------------------------------------------------------
extern "C" void kernel_launch(void* const* d_in, const int* in_sizes, int n_in,
                              void* d_out, int out_size)
{
    const float* pred   = (const float*)d_in[0];
    const float* target = (const float*)d_in[1];
    const int*   matid  = (const int*)  d_in[2];
    const float* strain = (const float*)d_in[3];
    const float* E_GPa  = (const float*)d_in[4];
    const float* temp   = (const float*)d_in[5];
    const float* sr     = (const float*)d_in[6];
    const float* mw     = (const float*)d_in[7];
    float* out = (float*)d_out;

    const int B = in_sizes[2];          // material_ids count
    const int S = in_sizes[0] / B;      // pred = B*S

    const int pairStrips = (B * B + STRIP - 1) / STRIP;   // 64 for B=128
    const int grid       = B + pairStrips;                 // 192 blocks

    fused_kernel<<<grid, 256>>>(pred, target, matid, strain, E_GPa, temp, sr, mw,
                                out, B, S, pairStrips);
}

// round 8
// speedup vs baseline: 1.1628x; 1.1628x over previous
#include <cuda_runtime.h>
#include <cuda_bf16.h>
#include <math.h>

// ---------------------------------------------------------------------------
// PhysicsAwareMSELoss — ONE fused kernel, lightweight scoped-atomic sync.
//   sample blocks (B): 256 threads x 8 elems; block reduces 7 sums; thread 0
//                      finishes per-sample math -> g_samp[4][b].
//   strip blocks (64): warp screens 32 fixed pairs (smem scalars), ballot-
//                      walks survivors in lane order, warp-reduces D only
//                      for needed pairs -> g_pairAcc[4][strip].
//   sync: thread 0 per block issues atom.add.release.gpu (NO __threadfence,
//         NO MEMBAR/CCTL.IVALL). Last block: acq_rel atom return gives
//         acquire; __syncthreads propagates; epilogue reads via __ldcg.
// ---------------------------------------------------------------------------

#define MAXB    256
#define MAXSTRP 256
#define ALPHA   0.7f
#define BETA    0.3f
#define STRIP   256     // pairs per strip block (8 warps x 32)

__device__ float g_samp[4][MAXB];        // 0:wmse 1:el_err 2:el_valid 3:mono
__device__ float g_pairAcc[4][MAXSTRP];  // 0:tsum 1:tcnt 2:ssum 3:scnt
__device__ unsigned int g_ticket;        // zero-init; reset by last block

__device__ __forceinline__ float reluf(float x) { return fmaxf(x, 0.f); }

__device__ __forceinline__ unsigned int ticket_add_acq_rel(unsigned int* p)
{
    unsigned int old;
    asm volatile("atom.add.acq_rel.gpu.u32 %0, [%1], 1;"
                 : "=r"(old) : "l"(p) : "memory");
    return old;
}

__device__ __forceinline__ void pair_masks(int mi, int mj,
                                           float sri, float srj,
                                           float ti, float tj,
                                           bool& tmask_ij, bool& smask_ij)
{
    bool same   = (mi == mj);
    float hi    = fmaxf(sri, srj);
    float lo    = fminf(sri, srj);
    float ratio = hi / (lo + 1e-8f);
    float tdiff = ti - tj;
    tmask_ij = same && (ratio <= 1.2f) && (fabsf(tdiff) >= 10.f) && (tdiff > 0.f);
    smask_ij = same && (fabsf(tdiff) <= 10.f) && (ratio >= 1.2f) && (sri > srj);
}

__global__ void __launch_bounds__(256)
fused_kernel(const float* __restrict__ pred,
             const float* __restrict__ target,
             const int*   __restrict__ mat,
             const float* __restrict__ strain,
             const float* __restrict__ E,
             const float* __restrict__ temp,
             const float* __restrict__ sr,
             const float* __restrict__ w,
             float* __restrict__ out,
             int B, int S, int nStrips)
{
    const int tid  = threadIdx.x;
    const int lane = tid & 31;
    const int wid  = tid >> 5;

    __shared__ float sh[8][8];
    __shared__ bool  sh_last;

    if (blockIdx.x < (unsigned)B) {
        // ---------------- one block per sample: stats + per-sample math ----------
        const int b = blockIdx.x;
        const float* p = pred   + (size_t)b * S;
        const float* t = target + (size_t)b * S;
        const float* e = strain + (size_t)b * S;

        float v[7];   // d2, cnt, sx, sy, sxy, sxx, mono
        #pragma unroll
        for (int k = 0; k < 7; k++) v[k] = 0.f;

        for (int base = 0; base < S; base += 2048) {
            const int e0 = base + tid * 8;
            if (e0 + 7 < S) {
                float4 p0 = *reinterpret_cast<const float4*>(p + e0);
                float4 p1 = *reinterpret_cast<const float4*>(p + e0 + 4);
                float4 t0 = *reinterpret_cast<const float4*>(t + e0);
                float4 t1 = *reinterpret_cast<const float4*>(t + e0 + 4);
                float4 ea = *reinterpret_cast<const float4*>(e + e0);
                float4 eb = *reinterpret_cast<const float4*>(e + e0 + 4);

                float pv[8] = {p0.x,p0.y,p0.z,p0.w,p1.x,p1.y,p1.z,p1.w};
                float tv[8] = {t0.x,t0.y,t0.z,t0.w,t1.x,t1.y,t1.z,t1.w};
                float ev[8] = {ea.x,ea.y,ea.z,ea.w,eb.x,eb.y,eb.z,eb.w};

                #pragma unroll
                for (int q = 0; q < 8; q++) {
                    float d = pv[q] - tv[q];
                    v[0] += d * d;
                    if (ev[q] < 0.02f) {
                        v[1] += 1.f; v[2] += ev[q]; v[3] += pv[q];
                        v[4] += ev[q] * pv[q]; v[5] += ev[q] * ev[q];
                    }
                }
                #pragma unroll
                for (int q = 0; q < 7; q++)
                    v[6] += reluf(pv[q] - pv[q + 1]);
                float nxt = __shfl_down_sync(0xFFFFFFFFu, pv[0], 1);
                if (lane == 31) nxt = (e0 + 8 < S) ? p[e0 + 8] : pv[7]; // => relu 0
                v[6] += reluf(pv[7] - nxt);
            } else if (e0 < S) {
                for (int i = e0; i < S && i < e0 + 8; i++) {
                    float pvv = p[i], tvv = t[i], evv = e[i];
                    float d = pvv - tvv; v[0] += d * d;
                    if (evv < 0.02f) { v[1] += 1.f; v[2] += evv; v[3] += pvv;
                                       v[4] += evv*pvv; v[5] += evv*evv; }
                    if (i < S - 1) v[6] += reluf(pvv - p[i + 1]);
                }
            }
        }

        #pragma unroll
        for (int k = 0; k < 7; k++) {
            #pragma unroll
            for (int off = 16; off > 0; off >>= 1)
                v[k] += __shfl_xor_sync(0xFFFFFFFFu, v[k], off);
        }
        if (lane == 0) {
            #pragma unroll
            for (int k = 0; k < 7; k++) sh[k][wid] = v[k];
        }
        __syncthreads();
        if (tid == 0) {
            float r[7];
            #pragma unroll
            for (int k = 0; k < 7; k++) {
                r[k] = 0.f;
                #pragma unroll
                for (int q = 0; q < 8; q++) r[k] += sh[k][q];
            }
            float wmse = (r[0] / (float)S) * w[mat[b]];
            float cnt = r[1], Sx = r[2], Sy = r[3], Sxy = r[4], Sxx = r[5];
            float el_err = 0.f, el_valid = 0.f;
            if (cnt >= 2.f) {
                float safe  = fmaxf(cnt, 1.f);
                float eps_m = Sx / safe;
                float sig_m = Sy / safe;
                float cov = Sxy - sig_m * Sx - eps_m * Sy + cnt * eps_m * sig_m;
                float var = Sxx - 2.f * eps_m * Sx + cnt * eps_m * eps_m;
                float et  = E[b] * 1000.f;
                el_err   = fabsf(cov / (var + 1e-8f) - et) / (et + 1e-8f);
                el_valid = 1.f;
            }
            g_samp[0][b] = wmse;
            g_samp[1][b] = el_err;
            g_samp[2][b] = el_valid;
            g_samp[3][b] = r[6];
        }
    } else {
        // ------------- strip of pairs: screen + sparse reduce + accumulate ------
        __shared__ int   s_mat[MAXB];
        __shared__ float s_sr[MAXB];
        __shared__ float s_temp[MAXB];

        const int strip = blockIdx.x - B;
        const int totalPairs = B * B;

        for (int b = tid; b < B; b += 256) {
            s_mat[b]  = mat[b];
            s_sr[b]   = sr[b];
            s_temp[b] = temp[b];
        }
        __syncthreads();

        const int idx = strip * STRIP + tid;
        bool t_ij = false, s_ji = false;
        int  myi = 0, myj = 0;
        if (idx < totalPairs) {
            myi = idx / B;
            myj = idx - myi * B;
            bool sd, td;
            pair_masks(s_mat[myi], s_mat[myj], s_sr[myi], s_sr[myj],
                       s_temp[myi], s_temp[myj], t_ij, sd);
            pair_masks(s_mat[myj], s_mat[myi], s_sr[myj], s_sr[myi],
                       s_temp[myj], s_temp[myi], td, s_ji);
        }
        const bool need = t_ij || s_ji;

        unsigned bal = __ballot_sync(0xFFFFFFFFu, need);
        float tsum = 0.f, tcnt = 0.f, ssum = 0.f, scnt = 0.f;
        const int S4 = S >> 2;
        while (bal) {
            const int src = __ffs(bal) - 1;
            bal &= bal - 1;
            const int i  = __shfl_sync(0xFFFFFFFFu, myi, src);
            const int j  = __shfl_sync(0xFFFFFFFFu, myj, src);
            const int tt = __shfl_sync(0xFFFFFFFFu, (int)t_ij, src);
            const int ss = __shfl_sync(0xFFFFFFFFu, (int)s_ji, src);

            const float4* si = reinterpret_cast<const float4*>(pred + (size_t)i * S);
            const float4* sj = reinterpret_cast<const float4*>(pred + (size_t)j * S);
            float acc = 0.f;
            #pragma unroll 4
            for (int k = lane; k < S4; k += 32) {
                float4 a = si[k], bq = sj[k];
                acc += reluf(a.x - bq.x) + reluf(a.y - bq.y)
                     + reluf(a.z - bq.z) + reluf(a.w - bq.w);
            }
            #pragma unroll
            for (int off = 16; off > 0; off >>= 1)
                acc += __shfl_xor_sync(0xFFFFFFFFu, acc, off);
            const float D = acc / (float)S;
            if (tt) { tsum += D; tcnt += 1.f; }
            if (ss) { ssum += D; scnt += 1.f; }
        }

        if (lane == 0) {
            sh[0][wid] = tsum; sh[1][wid] = tcnt;
            sh[2][wid] = ssum; sh[3][wid] = scnt;
        }
        __syncthreads();
        if (tid == 0) {
            float r0 = 0.f, r1 = 0.f, r2 = 0.f, r3 = 0.f;
            #pragma unroll
            for (int q = 0; q < 8; q++) {
                r0 += sh[0][q]; r1 += sh[1][q];
                r2 += sh[2][q]; r3 += sh[3][q];
            }
            g_pairAcc[0][strip] = r0;
            g_pairAcc[1][strip] = r1;
            g_pairAcc[2][strip] = r2;
            g_pairAcc[3][strip] = r3;
        }
    }

    // ============ sync: scoped atomic only (no MEMBAR anywhere) ============
    if (tid == 0) {
        // acq_rel: releases this thread's STGs above; acquire pairs with
        // every other block's release when this returns gridDim-1.
        unsigned int v = ticket_add_acq_rel(&g_ticket);
        sh_last = (v == gridDim.x - 1);
    }
    __syncthreads();      // extends thread 0's acquire to the whole block
    if (!sh_last) return;

    // ---- last block: sum 4*B + 4*nStrips floats (L2-direct), write scalar ----
    float acc8[8];
    #pragma unroll
    for (int k = 0; k < 8; k++) acc8[k] = 0.f;

    for (int b = tid; b < B; b += 256) {
        acc8[0] += __ldcg(&g_samp[0][b]);
        acc8[1] += __ldcg(&g_samp[1][b]);
        acc8[2] += __ldcg(&g_samp[2][b]);
        acc8[3] += __ldcg(&g_samp[3][b]);
    }
    for (int s = tid; s < nStrips; s += 256) {
        acc8[4] += __ldcg(&g_pairAcc[0][s]);
        acc8[5] += __ldcg(&g_pairAcc[1][s]);
        acc8[6] += __ldcg(&g_pairAcc[2][s]);
        acc8[7] += __ldcg(&g_pairAcc[3][s]);
    }

    #pragma unroll
    for (int k = 0; k < 8; k++) {
        #pragma unroll
        for (int off = 16; off > 0; off >>= 1)
            acc8[k] += __shfl_xor_sync(0xFFFFFFFFu, acc8[k], off);
    }
    __syncthreads();                 // sh[][] reuse
    if (lane == 0) {
        #pragma unroll
        for (int k = 0; k < 8; k++) sh[k][wid] = acc8[k];
    }
    __syncthreads();
    if (tid == 0) {
        float r[8];
        #pragma unroll
        for (int k = 0; k < 8; k++) {
            r[k] = 0.f;
            #pragma unroll
            for (int q = 0; q < 8; q++) r[k] += sh[k][q];
        }
        float mse_loss  = r[0] / (float)B;
        float elastic   = (r[2] > 0.f) ? r[1] / fmaxf(r[2], 1.f) : 0.f;
        float mono      = r[3] / (float)(B * (S - 1));
        float temp_loss = (r[5] > 0.f) ? r[4] / fmaxf(r[5], 1.f) : 0.f;
        float sr_loss   = (r[7] > 0.f) ? r[6] / fmaxf(r[7], 1.f) : 0.f;
        out[0] = ALPHA * mse_loss + BETA * (elastic + mono + temp_loss + sr_loss);
        g_ticket = 0;   // reset for next graph replay
    }
}

// --------------------------------------------------------------------------
extern "C" void kernel_launch(void* const* d_in, const int* in_sizes, int n_in,
                              void* d_out, int out_size)
{
    const float* pred   = (const float*)d_in[0];
    const float* target = (const float*)d_in[1];
    const int*   matid  = (const int*)  d_in[2];
    const float* strain = (const float*)d_in[3];
    const float* E_GPa  = (const float*)d_in[4];
    const float* temp   = (const float*)d_in[5];
    const float* sr     = (const float*)d_in[6];
    const float* mw     = (const float*)d_in[7];
    float* out = (float*)d_out;

    const int B = in_sizes[2];          // material_ids count
    const int S = in_sizes[0] / B;      // pred = B*S

    const int pairStrips = (B * B + STRIP - 1) / STRIP;   // 64 for B=128
    const int grid       = B + pairStrips;                 // 192 blocks

    fused_kernel<<<grid, 256>>>(pred, target, matid, strain, E_GPa, temp, sr, mw,
                                out, B, S, pairStrips);
}

// round 9
// speedup vs baseline: 1.1905x; 1.0238x over previous
#include <cuda_runtime.h>
#include <cuda_bf16.h>
#include <math.h>

// ---------------------------------------------------------------------------
// PhysicsAwareMSELoss — ONE fused kernel, scoped-atomic sync.
//   sample blocks (B): 256 threads x 8 elems; block reduces 7 sums; thread 0
//                      finishes per-sample math -> g_samp[4][b].
//   strip blocks (64): 256 threads screen 256 fixed pairs (smem scalars);
//                      survivors compacted block-wide via ballot+prefix
//                      (deterministic, no atomics), dealt round-robin to the
//                      8 warps; per pair: lane-strided loop with unroll 8
//                      (MLP 16) -> g_pairAcc[4][strip].
//   sync: thread 0 per block: atom.add.acq_rel.gpu (no MEMBAR anywhere).
//         Last block sums 768 floats via __ldcg, writes out[0], resets ticket.
// ---------------------------------------------------------------------------

#define MAXB    256
#define MAXSTRP 256
#define ALPHA   0.7f
#define BETA    0.3f
#define STRIP   256     // pairs screened per strip block

__device__ float g_samp[4][MAXB];        // 0:wmse 1:el_err 2:el_valid 3:mono
__device__ float g_pairAcc[4][MAXSTRP];  // 0:tsum 1:tcnt 2:ssum 3:scnt
__device__ unsigned int g_ticket;        // zero-init; reset by last block

__device__ __forceinline__ float reluf(float x) { return fmaxf(x, 0.f); }

__device__ __forceinline__ unsigned int ticket_add_acq_rel(unsigned int* p)
{
    unsigned int old;
    asm volatile("atom.add.acq_rel.gpu.u32 %0, [%1], 1;"
                 : "=r"(old) : "l"(p) : "memory");
    return old;
}

__device__ __forceinline__ void pair_masks(int mi, int mj,
                                           float sri, float srj,
                                           float ti, float tj,
                                           bool& tmask_ij, bool& smask_ij)
{
    bool same   = (mi == mj);
    float hi    = fmaxf(sri, srj);
    float lo    = fminf(sri, srj);
    float ratio = hi / (lo + 1e-8f);
    float tdiff = ti - tj;
    tmask_ij = same && (ratio <= 1.2f) && (fabsf(tdiff) >= 10.f) && (tdiff > 0.f);
    smask_ij = same && (fabsf(tdiff) <= 10.f) && (ratio >= 1.2f) && (sri > srj);
}

__global__ void __launch_bounds__(256)
fused_kernel(const float* __restrict__ pred,
             const float* __restrict__ target,
             const int*   __restrict__ mat,
             const float* __restrict__ strain,
             const float* __restrict__ E,
             const float* __restrict__ temp,
             const float* __restrict__ sr,
             const float* __restrict__ w,
             float* __restrict__ out,
             int B, int S, int nStrips)
{
    const int tid  = threadIdx.x;
    const int lane = tid & 31;
    const int wid  = tid >> 5;

    __shared__ float sh[8][8];
    __shared__ bool  sh_last;

    if (blockIdx.x < (unsigned)B) {
        // ---------------- one block per sample: stats + per-sample math ----------
        const int b = blockIdx.x;
        const float* p = pred   + (size_t)b * S;
        const float* t = target + (size_t)b * S;
        const float* e = strain + (size_t)b * S;

        float v[7];   // d2, cnt, sx, sy, sxy, sxx, mono
        #pragma unroll
        for (int k = 0; k < 7; k++) v[k] = 0.f;

        for (int base = 0; base < S; base += 2048) {
            const int e0 = base + tid * 8;
            if (e0 + 7 < S) {
                float4 p0 = *reinterpret_cast<const float4*>(p + e0);
                float4 p1 = *reinterpret_cast<const float4*>(p + e0 + 4);
                float4 t0 = *reinterpret_cast<const float4*>(t + e0);
                float4 t1 = *reinterpret_cast<const float4*>(t + e0 + 4);
                float4 ea = *reinterpret_cast<const float4*>(e + e0);
                float4 eb = *reinterpret_cast<const float4*>(e + e0 + 4);

                float pv[8] = {p0.x,p0.y,p0.z,p0.w,p1.x,p1.y,p1.z,p1.w};
                float tv[8] = {t0.x,t0.y,t0.z,t0.w,t1.x,t1.y,t1.z,t1.w};
                float ev[8] = {ea.x,ea.y,ea.z,ea.w,eb.x,eb.y,eb.z,eb.w};

                #pragma unroll
                for (int q = 0; q < 8; q++) {
                    float d = pv[q] - tv[q];
                    v[0] += d * d;
                    if (ev[q] < 0.02f) {
                        v[1] += 1.f; v[2] += ev[q]; v[3] += pv[q];
                        v[4] += ev[q] * pv[q]; v[5] += ev[q] * ev[q];
                    }
                }
                #pragma unroll
                for (int q = 0; q < 7; q++)
                    v[6] += reluf(pv[q] - pv[q + 1]);
                float nxt = __shfl_down_sync(0xFFFFFFFFu, pv[0], 1);
                if (lane == 31) nxt = (e0 + 8 < S) ? p[e0 + 8] : pv[7]; // => relu 0
                v[6] += reluf(pv[7] - nxt);
            } else if (e0 < S) {
                for (int i = e0; i < S && i < e0 + 8; i++) {
                    float pvv = p[i], tvv = t[i], evv = e[i];
                    float d = pvv - tvv; v[0] += d * d;
                    if (evv < 0.02f) { v[1] += 1.f; v[2] += evv; v[3] += pvv;
                                       v[4] += evv*pvv; v[5] += evv*evv; }
                    if (i < S - 1) v[6] += reluf(pvv - p[i + 1]);
                }
            }
        }

        #pragma unroll
        for (int k = 0; k < 7; k++) {
            #pragma unroll
            for (int off = 16; off > 0; off >>= 1)
                v[k] += __shfl_xor_sync(0xFFFFFFFFu, v[k], off);
        }
        if (lane == 0) {
            #pragma unroll
            for (int k = 0; k < 7; k++) sh[k][wid] = v[k];
        }
        __syncthreads();
        if (tid == 0) {
            float r[7];
            #pragma unroll
            for (int k = 0; k < 7; k++) {
                r[k] = 0.f;
                #pragma unroll
                for (int q = 0; q < 8; q++) r[k] += sh[k][q];
            }
            float wmse = (r[0] / (float)S) * w[mat[b]];
            float cnt = r[1], Sx = r[2], Sy = r[3], Sxy = r[4], Sxx = r[5];
            float el_err = 0.f, el_valid = 0.f;
            if (cnt >= 2.f) {
                float safe  = fmaxf(cnt, 1.f);
                float eps_m = Sx / safe;
                float sig_m = Sy / safe;
                float cov = Sxy - sig_m * Sx - eps_m * Sy + cnt * eps_m * sig_m;
                float var = Sxx - 2.f * eps_m * Sx + cnt * eps_m * eps_m;
                float et  = E[b] * 1000.f;
                el_err   = fabsf(cov / (var + 1e-8f) - et) / (et + 1e-8f);
                el_valid = 1.f;
            }
            g_samp[0][b] = wmse;
            g_samp[1][b] = el_err;
            g_samp[2][b] = el_valid;
            g_samp[3][b] = r[6];
        }
    } else {
        // ------- strip block: screen, deterministic compaction, balanced reduce -------
        __shared__ int   s_mat[MAXB];
        __shared__ float s_sr[MAXB];
        __shared__ float s_temp[MAXB];
        __shared__ int   s_list[STRIP];   // packed: (local_tid<<2)|(t_ij<<1)|s_ji
        __shared__ int   s_wcnt[8];
        __shared__ int   s_wbase[8];
        __shared__ int   s_total;

        const int strip = blockIdx.x - B;
        const int totalPairs = B * B;

        for (int b = tid; b < B; b += 256) {
            s_mat[b]  = mat[b];
            s_sr[b]   = sr[b];
            s_temp[b] = temp[b];
        }
        __syncthreads();

        // each thread screens exactly one fixed pair
        const int idx = strip * STRIP + tid;
        bool t_ij = false, s_ji = false;
        if (idx < totalPairs) {
            const int i = idx / B;
            const int j = idx - i * B;
            bool sd, td;
            pair_masks(s_mat[i], s_mat[j], s_sr[i], s_sr[j],
                       s_temp[i], s_temp[j], t_ij, sd);
            pair_masks(s_mat[j], s_mat[i], s_sr[j], s_sr[i],
                       s_temp[j], s_temp[i], td, s_ji);
        }
        const bool need = t_ij || s_ji;

        // deterministic block-wide compaction: ballot + per-warp prefix
        const unsigned bal  = __ballot_sync(0xFFFFFFFFu, need);
        const int      rank = __popc(bal & ((1u << lane) - 1u));
        if (lane == 0) s_wcnt[wid] = __popc(bal);
        __syncthreads();
        if (tid == 0) {
            int run = 0;
            #pragma unroll
            for (int q = 0; q < 8; q++) { s_wbase[q] = run; run += s_wcnt[q]; }
            s_total = run;
        }
        __syncthreads();
        if (need)
            s_list[s_wbase[wid] + rank] = (tid << 2) | ((int)t_ij << 1) | (int)s_ji;
        __syncthreads();

        // deal survivors round-robin to warps; high-MLP per-pair reduce
        const int total = s_total;
        float tsum = 0.f, tcnt = 0.f, ssum = 0.f, scnt = 0.f;
        const int S4 = S >> 2;
        for (int li = wid; li < total; li += 8) {
            const int packed = s_list[li];
            const int pidx   = strip * STRIP + (packed >> 2);
            const int tt     = (packed >> 1) & 1;
            const int ss     = packed & 1;
            const int i = pidx / B;
            const int j = pidx - i * B;

            const float4* si = reinterpret_cast<const float4*>(pred + (size_t)i * S);
            const float4* sj = reinterpret_cast<const float4*>(pred + (size_t)j * S);
            float acc = 0.f;
            #pragma unroll 8
            for (int k = lane; k < S4; k += 32) {
                float4 a = si[k], bq = sj[k];
                acc += reluf(a.x - bq.x) + reluf(a.y - bq.y)
                     + reluf(a.z - bq.z) + reluf(a.w - bq.w);
            }
            #pragma unroll
            for (int off = 16; off > 0; off >>= 1)
                acc += __shfl_xor_sync(0xFFFFFFFFu, acc, off);
            const float D = acc / (float)S;
            if (tt) { tsum += D; tcnt += 1.f; }
            if (ss) { ssum += D; scnt += 1.f; }
        }

        if (lane == 0) {
            sh[0][wid] = tsum; sh[1][wid] = tcnt;
            sh[2][wid] = ssum; sh[3][wid] = scnt;
        }
        __syncthreads();
        if (tid == 0) {
            float r0 = 0.f, r1 = 0.f, r2 = 0.f, r3 = 0.f;
            #pragma unroll
            for (int q = 0; q < 8; q++) {
                r0 += sh[0][q]; r1 += sh[1][q];
                r2 += sh[2][q]; r3 += sh[3][q];
            }
            g_pairAcc[0][strip] = r0;
            g_pairAcc[1][strip] = r1;
            g_pairAcc[2][strip] = r2;
            g_pairAcc[3][strip] = r3;
        }
    }

    // ============ sync: scoped atomic only (no MEMBAR anywhere) ============
    if (tid == 0) {
        unsigned int v = ticket_add_acq_rel(&g_ticket);
        sh_last = (v == gridDim.x - 1);
    }
    __syncthreads();
    if (!sh_last) return;

    // ---- last block: sum 4*B + 4*nStrips floats (L2-direct), write scalar ----
    float acc8[8];
    #pragma unroll
    for (int k = 0; k < 8; k++) acc8[k] = 0.f;

    for (int b = tid; b < B; b += 256) {
        acc8[0] += __ldcg(&g_samp[0][b]);
        acc8[1] += __ldcg(&g_samp[1][b]);
        acc8[2] += __ldcg(&g_samp[2][b]);
        acc8[3] += __ldcg(&g_samp[3][b]);
    }
    for (int s = tid; s < nStrips; s += 256) {
        acc8[4] += __ldcg(&g_pairAcc[0][s]);
        acc8[5] += __ldcg(&g_pairAcc[1][s]);
        acc8[6] += __ldcg(&g_pairAcc[2][s]);
        acc8[7] += __ldcg(&g_pairAcc[3][s]);
    }

    #pragma unroll
    for (int k = 0; k < 8; k++) {
        #pragma unroll
        for (int off = 16; off > 0; off >>= 1)
            acc8[k] += __shfl_xor_sync(0xFFFFFFFFu, acc8[k], off);
    }
    __syncthreads();                 // sh[][] reuse
    if (lane == 0) {
        #pragma unroll
        for (int k = 0; k < 8; k++) sh[k][wid] = acc8[k];
    }
    __syncthreads();
    if (tid == 0) {
        float r[8];
        #pragma unroll
        for (int k = 0; k < 8; k++) {
            r[k] = 0.f;
            #pragma unroll
            for (int q = 0; q < 8; q++) r[k] += sh[k][q];
        }
        float mse_loss  = r[0] / (float)B;
        float elastic   = (r[2] > 0.f) ? r[1] / fmaxf(r[2], 1.f) : 0.f;
        float mono      = r[3] / (float)(B * (S - 1));
        float temp_loss = (r[5] > 0.f) ? r[4] / fmaxf(r[5], 1.f) : 0.f;
        float sr_loss   = (r[7] > 0.f) ? r[6] / fmaxf(r[7], 1.f) : 0.f;
        out[0] = ALPHA * mse_loss + BETA * (elastic + mono + temp_loss + sr_loss);
        g_ticket = 0;   // reset for next graph replay
    }
}

// --------------------------------------------------------------------------
extern "C" void kernel_launch(void* const* d_in, const int* in_sizes, int n_in,
                              void* d_out, int out_size)
{
    const float* pred   = (const float*)d_in[0];
    const float* target = (const float*)d_in[1];
    const int*   matid  = (const int*)  d_in[2];
    const float* strain = (const float*)d_in[3];
    const float* E_GPa  = (const float*)d_in[4];
    const float* temp   = (const float*)d_in[5];
    const float* sr     = (const float*)d_in[6];
    const float* mw     = (const float*)d_in[7];
    float* out = (float*)d_out;

    const int B = in_sizes[2];          // material_ids count
    const int S = in_sizes[0] / B;      // pred = B*S

    const int pairStrips = (B * B + STRIP - 1) / STRIP;   // 64 for B=128
    const int grid       = B + pairStrips;                 // 192 blocks

    fused_kernel<<<grid, 256>>>(pred, target, matid, strain, E_GPa, temp, sr, mw,
                                out, B, S, pairStrips);
}